// round 9
// baseline (speedup 1.0000x reference)
#include <cuda_runtime.h>
#include <cuda_bf16.h>
#include <cstdint>

#define SQRT2F 1.41421356237309515f

// ---------------- scratch (allocation-free: __device__ globals) ----------------
__device__ float g_style[16 * 512];                 // style[b,i]
__device__ float g_demod[16 * 512];                 // demod[b,o]
__device__ float g_wsq[512 * 512];                  // sum_tap w[o,i,tap]^2
__device__ float g_wt[64 * 9 * 512 * 8];            // [c8][tap][o][perm-k]  (tf32)
__device__ float g_xmod[16 * 64 * 68 * 68 * 8];     // [b][c8][h2][w2][perm-k] padded, modulated (tf32)

// k-permutation: stored position p holds k = (p>>1) + ((p&1)<<2)
// (positions 2t,2t+1 hold the mma pair k=t, k=t+4)
__device__ __forceinline__ int kinv(int p) { return (p >> 1) + ((p & 1) << 2); }

__device__ __forceinline__ float f2tf32(float f) {
    unsigned r;
    asm("cvt.rna.tf32.f32 %0, %1;" : "=r"(r) : "f"(f));
    return __uint_as_float(r);
}

__device__ __forceinline__ void mma_tf32(float d[4],
                                         float a0, float a1, float a2, float a3,
                                         float b0, float b1) {
    asm volatile(
        "mma.sync.aligned.m16n8k8.row.col.f32.tf32.tf32.f32 "
        "{%0,%1,%2,%3}, {%4,%5,%6,%7}, {%8,%9}, {%0,%1,%2,%3};"
        : "+f"(d[0]), "+f"(d[1]), "+f"(d[2]), "+f"(d[3])
        : "r"(__float_as_uint(a0)), "r"(__float_as_uint(a1)),
          "r"(__float_as_uint(a2)), "r"(__float_as_uint(a3)),
          "r"(__float_as_uint(b0)), "r"(__float_as_uint(b1)));
}

__device__ __forceinline__ float lrelu2(float v) {
    return (v > 0.0f ? v : 0.2f * v) * SQRT2F;
}

__device__ __forceinline__ unsigned smem_u32(const void* p) {
    return (unsigned)__cvta_generic_to_shared(p);
}
__device__ __forceinline__ void cp16(unsigned dst, const void* src) {
    asm volatile("cp.async.cg.shared.global [%0], [%1], 16;\n" :: "r"(dst), "l"(src));
}

// ---------------- small kernels (fp32 exact) ----------------
__global__ void style_kernel(const float* __restrict__ latent,
                             const float* __restrict__ aw,
                             const float* __restrict__ ab) {
    int b = blockIdx.x;
    int tid = threadIdx.x, lane = tid & 31, warp = tid >> 5;
    __shared__ float lat[512];
    lat[tid] = latent[b * 512 + tid];
    __syncthreads();
    const float wmul = rsqrtf(512.0f);
    for (int n = 0; n < 32; n++) {
        int i = warp * 32 + n;
        const float* wr = aw + (size_t)i * 512;
        float p = 0.0f;
        #pragma unroll 4
        for (int k = lane; k < 512; k += 32) p += wr[k] * lat[k];
        #pragma unroll
        for (int off = 16; off; off >>= 1) p += __shfl_xor_sync(0xFFFFFFFFu, p, off);
        if (lane == 0) g_style[b * 512 + i] = lrelu2(p * wmul + ab[i]);
    }
}

__global__ void wsq_kernel(const float* __restrict__ cw) {
    int o = blockIdx.x, i = threadIdx.x;
    const float* p = cw + (size_t)o * 4608 + (size_t)i * 9;
    float s = 0.0f;
    #pragma unroll
    for (int t = 0; t < 9; t++) s += p[t] * p[t];
    g_wsq[o * 512 + i] = s;
}

__global__ void demod_kernel() {
    int b = blockIdx.x;
    int tid = threadIdx.x, lane = tid & 31, warp = tid >> 5;
    __shared__ float s2[512];
    float st = g_style[b * 512 + tid];
    s2[tid] = st * st;
    __syncthreads();
    for (int n = 0; n < 32; n++) {
        int o = warp * 32 + n;
        const float* wr = g_wsq + (size_t)o * 512;
        float p = 0.0f;
        #pragma unroll 4
        for (int k = lane; k < 512; k += 32) p += wr[k] * s2[k];
        #pragma unroll
        for (int off = 16; off; off >>= 1) p += __shfl_xor_sync(0xFFFFFFFFu, p, off);
        if (lane == 0) g_demod[b * 512 + o] = rsqrtf(p + 1e-8f);
    }
}

// ---------------- preprocess: weights -> [c8][tap][o][perm-k] (tf32) ----------------
__global__ void wt_kernel(const float* __restrict__ cw) {
    int c8 = blockIdx.x, tap = blockIdx.y, o = threadIdx.x;
    float* dst = g_wt + (((size_t)c8 * 9 + tap) * 512 + o) * 8;
    const float* src = cw + (size_t)o * 4608 + (size_t)c8 * 8 * 9 + tap;
    #pragma unroll
    for (int p = 0; p < 8; p++) dst[p] = f2tf32(src[kinv(p) * 9]);
}

// ---------------- preprocess: modulated + padded input -> [b][c8][68][68][perm-k] ----------------
__global__ void xmod_kernel(const float* __restrict__ x,
                            const float* __restrict__ noise,
                            const float* __restrict__ nw_p) {
    const int c8 = blockIdx.x, b = blockIdx.y;
    const int tid = threadIdx.x;
    __shared__ float xs[8][64];
    __shared__ float ns[64];
    __shared__ float sst[8];  // style per stored position p
    const float nw = *nw_p;
    if (tid < 8) sst[tid] = g_style[b * 512 + c8 * 8 + kinv(tid)];

    const float* xb  = x + ((size_t)b * 512 + c8 * 8) * 4096;
    const float* nzb = noise + (size_t)b * 4096;
    float* outb = g_xmod + ((size_t)b * 64 + c8) * (68 * 68 * 8);

    for (int h2 = 0; h2 < 68; h2++) {
        const bool hin = (h2 >= 1) && (h2 <= 64);
        if (hin) {
            int h = h2 - 1;
            #pragma unroll
            for (int j = tid; j < 512; j += 256) {
                int k = j >> 6, w = j & 63;
                xs[k][w] = xb[(size_t)k * 4096 + h * 64 + w];
            }
            if (tid < 64) ns[tid] = nzb[h * 64 + tid];
        }
        __syncthreads();
        float* orow = outb + (size_t)h2 * 68 * 8;
        #pragma unroll
        for (int j = tid; j < 544; j += 256) {
            int w2 = j >> 3, p = j & 7;
            float v = 0.0f;
            if (hin && w2 >= 1 && w2 <= 64) {
                int w = w2 - 1;
                v = f2tf32((xs[kinv(p)][w] + nw * ns[w]) * sst[p]);
            }
            orow[j] = v;
        }
        __syncthreads();
    }
}

// ---------------- main conv: implicit GEMM, tf32 mma.sync, cp.async 3-stage ----------------
// CTA: 128 cout x 256 pixels (4 rows). 8 warps (2m x 4n), warp tile 64x64.
// Stage (floats): Ws [9][128][8] = 9216, then Xs [6][68][8] = 3264. Stage = 12480.
#define STAGEF 12480
#define XS_OFF 9216
#define NSTAGE 3

__global__ __launch_bounds__(256, 1)
void conv_kernel(const float* __restrict__ bias, float* __restrict__ out) {
    extern __shared__ float smem[];

    const int b  = blockIdx.z;
    const int o0 = blockIdx.y * 128;
    const int p0 = blockIdx.x * 256;
    const int h0 = p0 >> 6;                    // first padded input row of the 6-row window
    const int tid = threadIdx.x;
    const int lane = tid & 31, warp = tid >> 5;
    const int wm = (warp >> 2) * 64;           // warp m offset: 0 or 64
    const int wr4 = warp & 3;                  // warp n-row: output row index 0..3 within tile
    const int g = lane >> 2, t = lane & 3;

    const float* xsrc_base = g_xmod + ((size_t)b * 64) * (68 * 68 * 8) + (size_t)h0 * 68 * 8;

    float d[4][8][4];
    #pragma unroll
    for (int mi = 0; mi < 4; mi++)
        #pragma unroll
        for (int nf = 0; nf < 8; nf++)
            #pragma unroll
            for (int j = 0; j < 4; j++) d[mi][nf][j] = 0.0f;

    auto fill = [&](int c0, int s) {
        float* stage = smem + s * STAGEF;
        // Ws: 9 taps x 1024 floats = 2304 float4
        #pragma unroll
        for (int r = 0; r < 9; r++) {
            int i = tid + r * 256;
            int tap = i >> 8, w4 = i & 255;
            const float* src = g_wt + (((size_t)c0 * 9 + tap) * 512 + o0) * 8 + w4 * 4;
            cp16(smem_u32(stage + tap * 1024 + w4 * 4), src);
        }
        // Xs: 6 rows x 68 x 8 = 3264 floats = 816 float4, fully contiguous
        const float* xsrc = xsrc_base + (size_t)c0 * (68 * 68 * 8);
        #pragma unroll
        for (int i = tid; i < 816; i += 256)
            cp16(smem_u32(stage + XS_OFF + i * 4), xsrc + i * 4);
    };

    fill(0, 0);
    asm volatile("cp.async.commit_group;\n");
    fill(1, 1);
    asm volatile("cp.async.commit_group;\n");

    int slot = 0;       // slot of chunk c
    int fslot = 2;      // slot for chunk c+2
    for (int c = 0; c < 64; c++) {
        asm volatile("cp.async.wait_group 1;\n");
        __syncthreads();
        if (c + 2 < 64) fill(c + 2, fslot);
        asm volatile("cp.async.commit_group;\n");

        const float* sW = smem + slot * STAGEF;
        const float* sX = sW + XS_OFF;

        #pragma unroll
        for (int tap = 0; tap < 9; tap++) {
            const int dy = tap / 3, dx = tap - dy * 3;
            float2 A0[4], A1[4];
            #pragma unroll
            for (int mi = 0; mi < 4; mi++) {
                int row = wm + mi * 16 + g;
                A0[mi] = *reinterpret_cast<const float2*>(sW + tap * 1024 + row * 8 + 2 * t);
                A1[mi] = *reinterpret_cast<const float2*>(sW + tap * 1024 + (row + 8) * 8 + 2 * t);
            }
            const float* xrow = sX + ((wr4 + dy) * 68 + g + dx) * 8 + 2 * t;
            #pragma unroll
            for (int nf = 0; nf < 8; nf++) {
                float2 Bv = *reinterpret_cast<const float2*>(xrow + nf * 64);
                #pragma unroll
                for (int mi = 0; mi < 4; mi++)
                    mma_tf32(d[mi][nf], A0[mi].x, A1[mi].x, A0[mi].y, A1[mi].y, Bv.x, Bv.y);
            }
        }
        slot = slot + 1 == NSTAGE ? 0 : slot + 1;
        fslot = fslot + 1 == NSTAGE ? 0 : fslot + 1;
    }

    // ---- epilogue: demod, bias, leaky-relu*sqrt2 ----
    const float* dm = g_demod + b * 512;
    #pragma unroll
    for (int mi = 0; mi < 4; mi++) {
        int o = o0 + wm + mi * 16 + g;
        float dem0 = dm[o],     bv0 = bias[o];
        float dem1 = dm[o + 8], bv1 = bias[o + 8];
        float* r0 = out + ((size_t)b * 512 + o) * 4096 + p0 + wr4 * 64;
        float* r1 = r0 + (size_t)8 * 4096;
        #pragma unroll
        for (int nf = 0; nf < 8; nf++) {
            int col = nf * 8 + 2 * t;
            float2 v0, v1;
            v0.x = lrelu2(d[mi][nf][0] * dem0 + bv0);
            v0.y = lrelu2(d[mi][nf][1] * dem0 + bv0);
            v1.x = lrelu2(d[mi][nf][2] * dem1 + bv1);
            v1.y = lrelu2(d[mi][nf][3] * dem1 + bv1);
            *reinterpret_cast<float2*>(r0 + col) = v0;
            *reinterpret_cast<float2*>(r1 + col) = v1;
        }
    }
}

// ---------------- launch ----------------
extern "C" void kernel_launch(void* const* d_in, const int* in_sizes, int n_in,
                              void* d_out, int out_size) {
    const float* x      = (const float*)d_in[0];
    const float* latent = (const float*)d_in[1];
    const float* noise  = (const float*)d_in[2];
    const float* aw     = (const float*)d_in[3];
    const float* ab     = (const float*)d_in[4];
    const float* cw     = (const float*)d_in[5];
    const float* nw     = (const float*)d_in[6];
    const float* bias   = (const float*)d_in[7];
    float* out = (float*)d_out;

    cudaFuncSetAttribute(conv_kernel, cudaFuncAttributeMaxDynamicSharedMemorySize,
                         NSTAGE * STAGEF * (int)sizeof(float));

    style_kernel<<<16, 512>>>(latent, aw, ab);
    wsq_kernel<<<512, 512>>>(cw);
    demod_kernel<<<16, 512>>>();
    wt_kernel<<<dim3(64, 9), 512>>>(cw);
    xmod_kernel<<<dim3(64, 16), 256>>>(x, noise, nw);
    conv_kernel<<<dim3(16, 4, 16), 256, NSTAGE * STAGEF * sizeof(float)>>>(bias, out);
}

// round 10
// speedup vs baseline: 1.1077x; 1.1077x over previous
#include <cuda_runtime.h>
#include <cuda_bf16.h>
#include <cstdint>

#define SQRT2F 1.41421356237309515f

// ---------------- scratch (allocation-free: __device__ globals) ----------------
__device__ float g_style[16 * 512];                    // style[b,i]
__device__ float g_demod[16 * 512];                    // demod[b,o]
__device__ float g_wsq[512 * 512];                     // sum_tap w[o,i,tap]^2
// U: [c8][comp4][dy3][o512][k8]  (tf32)  = 12.6 MB
__device__ float g_wt[64 * 4 * 3 * 512 * 8];
// V: [b][c8][comp4][row66][pair32][k8]   (tf32)  = 277 MB
__device__ float g_xm[(size_t)16 * 64 * 4 * 66 * 32 * 8];

// k-permutation: stored position p holds cin-offset kinv(p); pairs (2t,2t+1) = (t, t+4)
__device__ __forceinline__ int kinv(int p) { return (p >> 1) + ((p & 1) << 2); }

__device__ __forceinline__ float f2tf32(float f) {
    unsigned r;
    asm("cvt.rna.tf32.f32 %0, %1;" : "=r"(r) : "f"(f));
    return __uint_as_float(r);
}

__device__ __forceinline__ void mma_tf32(float d[4],
                                         float a0, float a1, float a2, float a3,
                                         float b0, float b1) {
    asm volatile(
        "mma.sync.aligned.m16n8k8.row.col.f32.tf32.tf32.f32 "
        "{%0,%1,%2,%3}, {%4,%5,%6,%7}, {%8,%9}, {%0,%1,%2,%3};"
        : "+f"(d[0]), "+f"(d[1]), "+f"(d[2]), "+f"(d[3])
        : "r"(__float_as_uint(a0)), "r"(__float_as_uint(a1)),
          "r"(__float_as_uint(a2)), "r"(__float_as_uint(a3)),
          "r"(__float_as_uint(b0)), "r"(__float_as_uint(b1)));
}

__device__ __forceinline__ float lrelu2(float v) {
    return (v > 0.0f ? v : 0.2f * v) * SQRT2F;
}

__device__ __forceinline__ unsigned smem_u32(const void* p) {
    return (unsigned)__cvta_generic_to_shared(p);
}
__device__ __forceinline__ void cp16(unsigned dst, const void* src) {
    asm volatile("cp.async.cg.shared.global [%0], [%1], 16;\n" :: "r"(dst), "l"(src));
}

// ---------------- launch 0: style (fp32 exact) ----------------
__global__ void style_kernel(const float* __restrict__ latent,
                             const float* __restrict__ aw,
                             const float* __restrict__ ab) {
    int b = blockIdx.x;
    int tid = threadIdx.x, lane = tid & 31, warp = tid >> 5;
    __shared__ float lat[512];
    lat[tid] = latent[b * 512 + tid];
    __syncthreads();
    const float wmul = rsqrtf(512.0f);
    for (int n = 0; n < 32; n++) {
        int i = warp * 32 + n;
        const float* wr = aw + (size_t)i * 512;
        float p = 0.0f;
        #pragma unroll 4
        for (int k = lane; k < 512; k += 32) p += wr[k] * lat[k];
        #pragma unroll
        for (int off = 16; off; off >>= 1) p += __shfl_xor_sync(0xFFFFFFFFu, p, off);
        if (lane == 0) g_style[b * 512 + i] = lrelu2(p * wmul + ab[i]);
    }
}

// ---------------- launch 1: wsq (blocks 0..511) + U weight transform (blocks 512..575) ----------------
__global__ void prep1_kernel(const float* __restrict__ cw) {
    if (blockIdx.x < 512) {
        int o = blockIdx.x, i = threadIdx.x;
        const float* p = cw + (size_t)o * 4608 + (size_t)i * 9;
        float s = 0.0f;
        #pragma unroll
        for (int t = 0; t < 9; t++) s += p[t] * p[t];
        g_wsq[o * 512 + i] = s;
        return;
    }
    // U-prep: c8 = blockIdx.x - 512, thread = o
    int c8 = blockIdx.x - 512, o = threadIdx.x;
    #pragma unroll
    for (int k = 0; k < 8; k++) {
        int cin = c8 * 8 + kinv(k);
        const float* src = cw + (size_t)o * 4608 + (size_t)cin * 9;
        #pragma unroll
        for (int dy = 0; dy < 3; dy++) {
            float g0 = src[dy * 3 + 0], g1 = src[dy * 3 + 1], g2 = src[dy * 3 + 2];
            float u0 = g0;
            float u1 = (g0 + g1 + g2) * 0.5f;
            float u2 = (g0 - g1 + g2) * 0.5f;
            float u3 = g2;
            size_t base = ((((size_t)c8 * 4 + 0) * 3 + dy) * 512 + o) * 8 + k;
            size_t cstr = (size_t)3 * 512 * 8;
            g_wt[base + 0 * cstr] = f2tf32(u0);
            g_wt[base + 1 * cstr] = f2tf32(u1);
            g_wt[base + 2 * cstr] = f2tf32(u2);
            g_wt[base + 3 * cstr] = f2tf32(u3);
        }
    }
}

// ---------------- launch 2: V input transform (bx<64) + demod (bx==64) ----------------
__global__ void prep2_kernel(const float* __restrict__ x,
                             const float* __restrict__ noise,
                             const float* __restrict__ nw_p) {
    const int b = blockIdx.y;
    const int tid = threadIdx.x;

    if (blockIdx.x == 64) {
        // demod[b,o] = rsqrt(sum_i wsq[o,i]*style[b,i]^2 + 1e-8), 256 threads
        __shared__ float s2[512];
        for (int i = tid; i < 512; i += 256) {
            float st = g_style[b * 512 + i];
            s2[i] = st * st;
        }
        __syncthreads();
        int lane = tid & 31, warp = tid >> 5;
        for (int n = 0; n < 64; n++) {
            int o = warp * 64 + n;
            const float* wr = g_wsq + (size_t)o * 512;
            float p = 0.0f;
            #pragma unroll 4
            for (int k = lane; k < 512; k += 32) p += wr[k] * s2[k];
            #pragma unroll
            for (int off = 16; off; off >>= 1) p += __shfl_xor_sync(0xFFFFFFFFu, p, off);
            if (lane == 0) g_demod[b * 512 + o] = rsqrtf(p + 1e-8f);
        }
        return;
    }

    // V-prep for (b, c8): rows 0..65 (padded), pairs 0..31, comps 0..3, k 0..7
    const int c8 = blockIdx.x;
    __shared__ float xp[8][66];   // padded modulated row per stored-k
    __shared__ float ns[64];
    __shared__ float sst[8];
    const float nw = *nw_p;
    if (tid < 8) sst[tid] = g_style[b * 512 + c8 * 8 + kinv(tid)];
    if (tid < 16) { int k = tid & 7; xp[k][(tid < 8) ? 0 : 65] = 0.0f; }

    const float* xb  = x + ((size_t)b * 512 + c8 * 8) * 4096;
    const float* nzb = noise + (size_t)b * 4096;
    float* outb = g_xm + ((size_t)b * 64 + c8) * (4 * 66 * 32 * 8);
    const size_t cplane = (size_t)66 * 32 * 8;   // 16896

    for (int row = 0; row < 66; row++) {
        int h = row - 1;
        bool hin = (unsigned)h < 64u;
        __syncthreads();
        if (hin) {
            if (tid < 64) ns[tid] = nzb[h * 64 + tid];
            __syncthreads();
            #pragma unroll
            for (int j = tid; j < 512; j += 256) {
                int k = j >> 6, w = j & 63;
                float xv = xb[(size_t)kinv(k) * 4096 + h * 64 + w];
                xp[k][1 + w] = (xv + nw * ns[w]) * sst[k];
            }
        } else {
            #pragma unroll
            for (int j = tid; j < 512; j += 256) {
                int k = j >> 6, w = j & 63;
                xp[k][1 + w] = 0.0f;
            }
        }
        __syncthreads();
        // tid -> (pair, k): pair = tid>>3, k = tid&7
        int pc = tid >> 3, k = tid & 7;
        float d0 = xp[k][2 * pc + 0];
        float d1 = xp[k][2 * pc + 1];
        float d2 = xp[k][2 * pc + 2];
        float d3 = xp[k][2 * pc + 3];
        float* orow = outb + (size_t)row * 256 + tid;
        orow[0 * cplane] = f2tf32(d0 - d2);
        orow[1 * cplane] = f2tf32(d1 + d2);
        orow[2 * cplane] = f2tf32(d2 - d1);
        orow[3 * cplane] = f2tf32(d1 - d3);
    }
}

// ---------------- launch 3: conv — Winograd F(2,3)-width, tf32 mma.sync, 2-stage cp.async ----------------
// CTA: 128 cout x 128 pixels (2 output rows = 64 pairs). N_gemm = 4 comps x 64 pairs = 256.
// 8 warps: wm = (warp>>2)*64 (cout), wc = warp&3 (component). Warp GEMM: 64 x 64(pairs) per comp.
// Stage floats: Us [comp4][dy3][o128][k8] = 12288, Vs [comp4][row4][pair32][k8] = 4096. STAGEF = 16384.
#define STAGEF 16384
#define VS_OFF 12288
#define EPL 66          // epilogue plane pair-stride
#define SMEMF 33792     // max(2*STAGEF, 4*128*EPL) = 33792 floats = 135168 B

__global__ __launch_bounds__(256, 1)
void conv_kernel(const float* __restrict__ bias, float* __restrict__ out) {
    extern __shared__ float smem[];

    const int b  = blockIdx.z;
    const int o0 = blockIdx.y * 128;
    const int pt = blockIdx.x;          // pixel tile: 2 output rows
    const int h0 = pt * 2;
    const int tid = threadIdx.x;
    const int lane = tid & 31, warp = tid >> 5;
    const int wm = (warp >> 2) * 64;
    const int wc = warp & 3;            // component
    const int g = lane >> 2, t = lane & 3;

    const float* vsrc_base = g_xm + ((size_t)b * 64) * (4 * 66 * 32 * 8);

    float d[4][8][4];
    #pragma unroll
    for (int mi = 0; mi < 4; mi++)
        #pragma unroll
        for (int nf = 0; nf < 8; nf++)
            #pragma unroll
            for (int j = 0; j < 4; j++) d[mi][nf][j] = 0.0f;

    auto fill = [&](int c8, int s) {
        float* stage = smem + s * STAGEF;
        // Us: 12 slabs (comp,dy) x 1024 floats, contiguous both sides
        #pragma unroll
        for (int i = 0; i < 12; i++) {
            int idx = tid + i * 256;
            int slab = idx >> 8, w4 = idx & 255;
            const float* src = g_wt + ((size_t)c8 * 12 + slab) * 4096 + (size_t)o0 * 8 + w4 * 4;
            cp16(smem_u32(stage + slab * 1024 + w4 * 4), src);
        }
        // Vs: 4 comps x (4 rows x 32 pairs x 8) = 4 x 1024 floats, contiguous per comp
        const float* vsrc = vsrc_base + (size_t)c8 * (4 * 66 * 32 * 8) + (size_t)h0 * 256;
        #pragma unroll
        for (int i = 0; i < 4; i++) {
            int idx = tid + i * 256;
            int comp = idx >> 8, w4 = idx & 255;
            cp16(smem_u32(stage + VS_OFF + comp * 1024 + w4 * 4),
                 vsrc + (size_t)comp * (66 * 32 * 8) + w4 * 4);
        }
    };

    fill(0, 0);
    asm volatile("cp.async.commit_group;\n");

    for (int c = 0; c < 64; c++) {
        if (c + 1 < 64) fill(c + 1, (c + 1) & 1);
        asm volatile("cp.async.commit_group;\n");
        asm volatile("cp.async.wait_group 1;\n");
        __syncthreads();

        const float* sU = smem + (c & 1) * STAGEF;
        const float* sV = sU + VS_OFF;

        #pragma unroll
        for (int dy = 0; dy < 3; dy++) {
            const float* slab = sU + (wc * 3 + dy) * 1024;
            float2 A0[4], A1[4];
            #pragma unroll
            for (int mi = 0; mi < 4; mi++) {
                int row = wm + mi * 16 + g;
                A0[mi] = *reinterpret_cast<const float2*>(slab + row * 8 + 2 * t);
                A1[mi] = *reinterpret_cast<const float2*>(slab + (row + 8) * 8 + 2 * t);
            }
            #pragma unroll
            for (int nf = 0; nf < 8; nf++) {
                int irow = (nf >> 2) + dy;              // input row 0..3 in stage
                int pair = (nf & 3) * 8 + g;            // pair 0..31
                float2 Bv = *reinterpret_cast<const float2*>(
                    sV + ((wc * 4 + irow) * 32 + pair) * 8 + 2 * t);
                #pragma unroll
                for (int mi = 0; mi < 4; mi++)
                    mma_tf32(d[mi][nf], A0[mi].x, A1[mi].x, A0[mi].y, A1[mi].y, Bv.x, Bv.y);
            }
        }
        __syncthreads();
    }
    asm volatile("cp.async.wait_group 0;\n");
    __syncthreads();

    // ---- epilogue phase 1: dump m-planes [comp][m128][pair64 stride EPL] to smem ----
    #pragma unroll
    for (int mi = 0; mi < 4; mi++) {
        int m0 = wm + mi * 16 + g;
        #pragma unroll
        for (int nf = 0; nf < 8; nf++) {
            // fragment cols: pairs nf*8 + 2t, +1 ; rows m0 (j0,j1) and m0+8 (j2,j3)
            int pr = nf * 8 + 2 * t;
            float* p0 = smem + (size_t)wc * (128 * EPL) + m0 * EPL + pr;
            float* p1 = p0 + 8 * EPL;
            p0[0] = d[mi][nf][0]; p0[1] = d[mi][nf][1];
            p1[0] = d[mi][nf][2]; p1[1] = d[mi][nf][3];
        }
    }
    __syncthreads();

    // ---- epilogue phase 2: y0 = m0+m1+m2, y1 = m1-m2-m3; demod/bias/lrelu; store ----
    const float* dm = g_demod + b * 512;
    #pragma unroll
    for (int it = 0; it < 32; it++) {
        int idx = it * 256 + tid;          // (m, pair)
        int m = idx >> 6, pair = idx & 63;
        const float* pm = smem + m * EPL + pair;
        float m0 = pm[0 * 128 * EPL];
        float m1 = pm[1 * 128 * EPL];
        float m2 = pm[2 * 128 * EPL];
        float m3 = pm[3 * 128 * EPL];
        int o = o0 + m;
        float dem = dm[o], bv = bias[o];
        float2 v;
        v.x = lrelu2((m0 + m1 + m2) * dem + bv);
        v.y = lrelu2((m1 - m2 - m3) * dem + bv);
        int row = h0 + (pair >> 5);
        int col = (pair & 31) * 2;
        *reinterpret_cast<float2*>(out + ((size_t)b * 512 + o) * 4096 + row * 64 + col) = v;
    }
}

// ---------------- launch ----------------
extern "C" void kernel_launch(void* const* d_in, const int* in_sizes, int n_in,
                              void* d_out, int out_size) {
    const float* x      = (const float*)d_in[0];
    const float* latent = (const float*)d_in[1];
    const float* noise  = (const float*)d_in[2];
    const float* aw     = (const float*)d_in[3];
    const float* ab     = (const float*)d_in[4];
    const float* cw     = (const float*)d_in[5];
    const float* nw     = (const float*)d_in[6];
    const float* bias   = (const float*)d_in[7];
    float* out = (float*)d_out;

    cudaFuncSetAttribute(conv_kernel, cudaFuncAttributeMaxDynamicSharedMemorySize,
                         SMEMF * (int)sizeof(float));

    style_kernel<<<16, 512>>>(latent, aw, ab);
    prep1_kernel<<<576, 512>>>(cw);
    prep2_kernel<<<dim3(65, 16), 256>>>(x, noise, nw);
    conv_kernel<<<dim3(32, 4, 16), 256, SMEMF * sizeof(float)>>>(bias, out);
}

// round 13
// speedup vs baseline: 1.1124x; 1.0043x over previous
#include <cuda_runtime.h>
#include <cuda_bf16.h>
#include <cstdint>

#define SQRT2F 1.41421356237309515f

// ---------------- scratch (allocation-free: __device__ globals) ----------------
__device__ float g_style[16 * 512];                    // style[b,i]
__device__ float g_demod[16 * 512];                    // demod[b,o]
__device__ float g_wsq[512 * 512];                     // sum_tap w[o,i,tap]^2
// U: [c8][comp4][dy3][o512][k8]  (tf32)
__device__ float g_wt[64 * 4 * 3 * 512 * 8];
// V: [b][c8][comp4][row66][pair32][k8]   (tf32)
__device__ float g_xm[(size_t)16 * 64 * 4 * 66 * 32 * 8];

// k-permutation: stored position p holds cin-offset kinv(p); pairs (2t,2t+1) = (t, t+4)
__device__ __forceinline__ int kinv(int p) { return (p >> 1) + ((p & 1) << 2); }

__device__ __forceinline__ float f2tf32(float f) {
    unsigned r;
    asm("cvt.rna.tf32.f32 %0, %1;" : "=r"(r) : "f"(f));
    return __uint_as_float(r);
}

__device__ __forceinline__ void mma_tf32(float d[4],
                                         float a0, float a1, float a2, float a3,
                                         float b0, float b1) {
    asm volatile(
        "mma.sync.aligned.m16n8k8.row.col.f32.tf32.tf32.f32 "
        "{%0,%1,%2,%3}, {%4,%5,%6,%7}, {%8,%9}, {%0,%1,%2,%3};"
        : "+f"(d[0]), "+f"(d[1]), "+f"(d[2]), "+f"(d[3])
        : "r"(__float_as_uint(a0)), "r"(__float_as_uint(a1)),
          "r"(__float_as_uint(a2)), "r"(__float_as_uint(a3)),
          "r"(__float_as_uint(b0)), "r"(__float_as_uint(b1)));
}

__device__ __forceinline__ float lrelu2(float v) {
    return (v > 0.0f ? v : 0.2f * v) * SQRT2F;
}

__device__ __forceinline__ unsigned smem_u32(const void* p) {
    return (unsigned)__cvta_generic_to_shared(p);
}
__device__ __forceinline__ void cp16(unsigned dst, const void* src) {
    asm volatile("cp.async.cg.shared.global [%0], [%1], 16;\n" :: "r"(dst), "l"(src));
}

// ---------------- launch 0: style (fp32 exact) ----------------
__global__ void style_kernel(const float* __restrict__ latent,
                             const float* __restrict__ aw,
                             const float* __restrict__ ab) {
    int b = blockIdx.x;
    int tid = threadIdx.x, lane = tid & 31, warp = tid >> 5;
    __shared__ float lat[512];
    lat[tid] = latent[b * 512 + tid];
    __syncthreads();
    const float wmul = rsqrtf(512.0f);
    for (int n = 0; n < 32; n++) {
        int i = warp * 32 + n;
        const float* wr = aw + (size_t)i * 512;
        float p = 0.0f;
        #pragma unroll 4
        for (int k = lane; k < 512; k += 32) p += wr[k] * lat[k];
        #pragma unroll
        for (int off = 16; off; off >>= 1) p += __shfl_xor_sync(0xFFFFFFFFu, p, off);
        if (lane == 0) g_style[b * 512 + i] = lrelu2(p * wmul + ab[i]);
    }
}

// ---------------- launch 1: wsq (blocks 0..511) + U weight transform (blocks 512..575) ----------------
__global__ void prep1_kernel(const float* __restrict__ cw) {
    if (blockIdx.x < 512) {
        int o = blockIdx.x, i = threadIdx.x;
        const float* p = cw + (size_t)o * 4608 + (size_t)i * 9;
        float s = 0.0f;
        #pragma unroll
        for (int t = 0; t < 9; t++) s += p[t] * p[t];
        g_wsq[o * 512 + i] = s;
        return;
    }
    int c8 = blockIdx.x - 512, o = threadIdx.x;
    #pragma unroll
    for (int k = 0; k < 8; k++) {
        int cin = c8 * 8 + kinv(k);
        const float* src = cw + (size_t)o * 4608 + (size_t)cin * 9;
        #pragma unroll
        for (int dy = 0; dy < 3; dy++) {
            float g0 = src[dy * 3 + 0], g1 = src[dy * 3 + 1], g2 = src[dy * 3 + 2];
            float u0 = g0;
            float u1 = (g0 + g1 + g2) * 0.5f;
            float u2 = (g0 - g1 + g2) * 0.5f;
            float u3 = g2;
            size_t base = ((((size_t)c8 * 4 + 0) * 3 + dy) * 512 + o) * 8 + k;
            size_t cstr = (size_t)3 * 512 * 8;
            g_wt[base + 0 * cstr] = f2tf32(u0);
            g_wt[base + 1 * cstr] = f2tf32(u1);
            g_wt[base + 2 * cstr] = f2tf32(u2);
            g_wt[base + 3 * cstr] = f2tf32(u3);
        }
    }
}

// ---------------- launch 2: V input transform (bx<64) + demod (bx==64) ----------------
__global__ void prep2_kernel(const float* __restrict__ x,
                             const float* __restrict__ noise,
                             const float* __restrict__ nw_p) {
    const int b = blockIdx.y;
    const int tid = threadIdx.x;

    if (blockIdx.x == 64) {
        __shared__ float s2[512];
        for (int i = tid; i < 512; i += 256) {
            float st = g_style[b * 512 + i];
            s2[i] = st * st;
        }
        __syncthreads();
        int lane = tid & 31, warp = tid >> 5;
        for (int n = 0; n < 64; n++) {
            int o = warp * 64 + n;
            const float* wr = g_wsq + (size_t)o * 512;
            float p = 0.0f;
            #pragma unroll 4
            for (int k = lane; k < 512; k += 32) p += wr[k] * s2[k];
            #pragma unroll
            for (int off = 16; off; off >>= 1) p += __shfl_xor_sync(0xFFFFFFFFu, p, off);
            if (lane == 0) g_demod[b * 512 + o] = rsqrtf(p + 1e-8f);
        }
        return;
    }

    const int c8 = blockIdx.x;
    __shared__ float xp[8][66];
    __shared__ float ns[64];
    __shared__ float sst[8];
    const float nw = *nw_p;
    if (tid < 8) sst[tid] = g_style[b * 512 + c8 * 8 + kinv(tid)];
    if (tid < 16) { int k = tid & 7; xp[k][(tid < 8) ? 0 : 65] = 0.0f; }

    const float* xb  = x + ((size_t)b * 512 + c8 * 8) * 4096;
    const float* nzb = noise + (size_t)b * 4096;
    float* outb = g_xm + ((size_t)b * 64 + c8) * (4 * 66 * 32 * 8);
    const size_t cplane = (size_t)66 * 32 * 8;

    for (int row = 0; row < 66; row++) {
        int h = row - 1;
        bool hin = (unsigned)h < 64u;
        __syncthreads();
        if (hin) {
            if (tid < 64) ns[tid] = nzb[h * 64 + tid];
            __syncthreads();
            #pragma unroll
            for (int j = tid; j < 512; j += 256) {
                int k = j >> 6, w = j & 63;
                float xv = xb[(size_t)kinv(k) * 4096 + h * 64 + w];
                xp[k][1 + w] = (xv + nw * ns[w]) * sst[k];
            }
        } else {
            #pragma unroll
            for (int j = tid; j < 512; j += 256) {
                int k = j >> 6, w = j & 63;
                xp[k][1 + w] = 0.0f;
            }
        }
        __syncthreads();
        int pc = tid >> 3, k = tid & 7;
        float d0 = xp[k][2 * pc + 0];
        float d1 = xp[k][2 * pc + 1];
        float d2 = xp[k][2 * pc + 2];
        float d3 = xp[k][2 * pc + 3];
        float* orow = outb + (size_t)row * 256 + tid;
        orow[0 * cplane] = f2tf32(d0 - d2);
        orow[1 * cplane] = f2tf32(d1 + d2);
        orow[2 * cplane] = f2tf32(d2 - d1);
        orow[3 * cplane] = f2tf32(d1 - d3);
    }
}

// ---------------- launch 3: conv — Winograd F(2,3)-width, tf32 mma.sync ----------------
// CTA: 128 cout x 128 pixels (2 output rows = 64 pairs), 512 threads / 16 warps.
// Warp (wmrow = warp>>2, wc = warp&3): 32 cout x 64 pairs for component wc.
// Stage floats: Us [comp4][dy3][o128][k8] = 12288, Vs [comp4][row4][pair32][k8] = 4096. STAGEF = 16384.
#define STAGEF 16384
#define VS_OFF 12288
#define EPL 66
#define SMEMF 33792     // max(2*STAGEF, 4*128*EPL)

__global__ __launch_bounds__(512, 1)
void conv_kernel(const float* __restrict__ bias, float* __restrict__ out) {
    extern __shared__ float smem[];

    const int b  = blockIdx.z;
    const int o0 = blockIdx.y * 128;
    const int pt = blockIdx.x;
    const int h0 = pt * 2;
    const int tid = threadIdx.x;
    const int lane = tid & 31, warp = tid >> 5;
    const int wm = (warp >> 2) * 32;     // cout offset: 0,32,64,96
    const int wc = warp & 3;             // Winograd component
    const int g = lane >> 2, t = lane & 3;

    const float* vsrc_base = g_xm + ((size_t)b * 64) * (4 * 66 * 32 * 8);

    float d[2][8][4];
    #pragma unroll
    for (int mi = 0; mi < 2; mi++)
        #pragma unroll
        for (int nf = 0; nf < 8; nf++)
            #pragma unroll
            for (int j = 0; j < 4; j++) d[mi][nf][j] = 0.0f;

    auto fill = [&](int c8, int s) {
        float* stage = smem + s * STAGEF;
        // Us: 12 slabs x 1024 floats = 3072 float4
        #pragma unroll
        for (int i = 0; i < 6; i++) {
            int idx = tid + i * 512;
            int slab = idx >> 8, w4 = idx & 255;
            const float* src = g_wt + ((size_t)c8 * 12 + slab) * 4096 + (size_t)o0 * 8 + w4 * 4;
            cp16(smem_u32(stage + slab * 1024 + w4 * 4), src);
        }
        // Vs: 4 comps x 1024 floats = 1024 float4
        const float* vsrc = vsrc_base + (size_t)c8 * (4 * 66 * 32 * 8) + (size_t)h0 * 256;
        #pragma unroll
        for (int i = 0; i < 2; i++) {
            int idx = tid + i * 512;
            int comp = idx >> 8, w4 = idx & 255;
            cp16(smem_u32(stage + VS_OFF + comp * 1024 + w4 * 4),
                 vsrc + (size_t)comp * (66 * 32 * 8) + w4 * 4);
        }
    };

    fill(0, 0);
    asm volatile("cp.async.commit_group;\n");

    for (int c = 0; c < 64; c++) {
        if (c + 1 < 64) fill(c + 1, (c + 1) & 1);
        asm volatile("cp.async.commit_group;\n");
        asm volatile("cp.async.wait_group 1;\n");
        __syncthreads();

        const float* sU = smem + (c & 1) * STAGEF;
        const float* sV = sU + VS_OFF;

        #pragma unroll
        for (int dy = 0; dy < 3; dy++) {
            const float* slab = sU + (wc * 3 + dy) * 1024;
            float2 A0[2], A1[2];
            #pragma unroll
            for (int mi = 0; mi < 2; mi++) {
                int row = wm + mi * 16 + g;
                A0[mi] = *reinterpret_cast<const float2*>(slab + row * 8 + 2 * t);
                A1[mi] = *reinterpret_cast<const float2*>(slab + (row + 8) * 8 + 2 * t);
            }
            #pragma unroll
            for (int nf = 0; nf < 8; nf++) {
                int irow = (nf >> 2) + dy;
                int pair = (nf & 3) * 8 + g;
                float2 Bv = *reinterpret_cast<const float2*>(
                    sV + ((wc * 4 + irow) * 32 + pair) * 8 + 2 * t);
                #pragma unroll
                for (int mi = 0; mi < 2; mi++)
                    mma_tf32(d[mi][nf], A0[mi].x, A1[mi].x, A0[mi].y, A1[mi].y, Bv.x, Bv.y);
            }
        }
        __syncthreads();
    }
    asm volatile("cp.async.wait_group 0;\n");
    __syncthreads();

    // ---- epilogue phase 1: dump m-planes [comp][m128][pair stride EPL] to smem ----
    #pragma unroll
    for (int mi = 0; mi < 2; mi++) {
        int m0 = wm + mi * 16 + g;
        #pragma unroll
        for (int nf = 0; nf < 8; nf++) {
            int pr = nf * 8 + 2 * t;
            float* p0 = smem + (size_t)wc * (128 * EPL) + m0 * EPL + pr;
            float* p1 = p0 + 8 * EPL;
            p0[0] = d[mi][nf][0]; p0[1] = d[mi][nf][1];
            p1[0] = d[mi][nf][2]; p1[1] = d[mi][nf][3];
        }
    }
    __syncthreads();

    // ---- epilogue phase 2: y0 = m0+m1+m2, y1 = m1-m2-m3; demod/bias/lrelu; store ----
    const float* dm = g_demod + b * 512;
    #pragma unroll
    for (int it = 0; it < 16; it++) {
        int idx = it * 512 + tid;          // (m, pair)
        int m = idx >> 6, pair = idx & 63;
        const float* pm = smem + m * EPL + pair;
        float m0 = pm[0 * 128 * EPL];
        float m1 = pm[1 * 128 * EPL];
        float m2 = pm[2 * 128 * EPL];
        float m3 = pm[3 * 128 * EPL];
        int o = o0 + m;
        float dem = dm[o], bv = bias[o];
        float2 v;
        v.x = lrelu2((m0 + m1 + m2) * dem + bv);
        v.y = lrelu2((m1 - m2 - m3) * dem + bv);
        int row = h0 + (pair >> 5);
        int col = (pair & 31) * 2;
        *reinterpret_cast<float2*>(out + ((size_t)b * 512 + o) * 4096 + row * 64 + col) = v;
    }
}

// ---------------- launch ----------------
extern "C" void kernel_launch(void* const* d_in, const int* in_sizes, int n_in,
                              void* d_out, int out_size) {
    const float* x      = (const float*)d_in[0];
    const float* latent = (const float*)d_in[1];
    const float* noise  = (const float*)d_in[2];
    const float* aw     = (const float*)d_in[3];
    const float* ab     = (const float*)d_in[4];
    const float* cw     = (const float*)d_in[5];
    const float* nw     = (const float*)d_in[6];
    const float* bias   = (const float*)d_in[7];
    float* out = (float*)d_out;

    cudaFuncSetAttribute(conv_kernel, cudaFuncAttributeMaxDynamicSharedMemorySize,
                         SMEMF * (int)sizeof(float));

    style_kernel<<<16, 512>>>(latent, aw, ab);
    prep1_kernel<<<576, 512>>>(cw);
    prep2_kernel<<<dim3(65, 16), 256>>>(x, noise, nw);
    conv_kernel<<<dim3(32, 4, 16), 512, SMEMF * sizeof(float)>>>(bias, out);
}

// round 15
// speedup vs baseline: 1.2024x; 1.0809x over previous
#include <cuda_runtime.h>
#include <cuda_bf16.h>
#include <cstdint>

#define SQRT2F 1.41421356237309515f

// ---------------- scratch (allocation-free: __device__ globals) ----------------
__device__ float g_style[16 * 512];
__device__ float g_demod[16 * 512];
__device__ float g_wsq[512 * 512];
// U: [c8][comp4][dy3][o512][k8]  (tf32)
__device__ float g_wt[64 * 4 * 3 * 512 * 8];
// V: [b][c8][comp4][row66][pair32][k8]   (tf32)
__device__ float g_xm[(size_t)16 * 64 * 4 * 66 * 32 * 8];

__device__ __forceinline__ int kinv(int p) { return (p >> 1) + ((p & 1) << 2); }

__device__ __forceinline__ float f2tf32(float f) {
    unsigned r;
    asm("cvt.rna.tf32.f32 %0, %1;" : "=r"(r) : "f"(f));
    return __uint_as_float(r);
}

__device__ __forceinline__ void mma_tf32(float d[4],
                                         float a0, float a1, float a2, float a3,
                                         float b0, float b1) {
    asm volatile(
        "mma.sync.aligned.m16n8k8.row.col.f32.tf32.tf32.f32 "
        "{%0,%1,%2,%3}, {%4,%5,%6,%7}, {%8,%9}, {%0,%1,%2,%3};"
        : "+f"(d[0]), "+f"(d[1]), "+f"(d[2]), "+f"(d[3])
        : "r"(__float_as_uint(a0)), "r"(__float_as_uint(a1)),
          "r"(__float_as_uint(a2)), "r"(__float_as_uint(a3)),
          "r"(__float_as_uint(b0)), "r"(__float_as_uint(b1)));
}

__device__ __forceinline__ float lrelu2(float v) {
    return (v > 0.0f ? v : 0.2f * v) * SQRT2F;
}

__device__ __forceinline__ unsigned smem_u32(const void* p) {
    return (unsigned)__cvta_generic_to_shared(p);
}
__device__ __forceinline__ void cp16(unsigned dst, const void* src) {
    asm volatile("cp.async.cg.shared.global [%0], [%1], 16;\n" :: "r"(dst), "l"(src));
}

// ---------------- launch 0: style (fp32 exact) ----------------
__global__ void style_kernel(const float* __restrict__ latent,
                             const float* __restrict__ aw,
                             const float* __restrict__ ab) {
    int b = blockIdx.x;
    int tid = threadIdx.x, lane = tid & 31, warp = tid >> 5;
    __shared__ float lat[512];
    lat[tid] = latent[b * 512 + tid];
    __syncthreads();
    const float wmul = rsqrtf(512.0f);
    for (int n = 0; n < 32; n++) {
        int i = warp * 32 + n;
        const float* wr = aw + (size_t)i * 512;
        float p = 0.0f;
        #pragma unroll 4
        for (int k = lane; k < 512; k += 32) p += wr[k] * lat[k];
        #pragma unroll
        for (int off = 16; off; off >>= 1) p += __shfl_xor_sync(0xFFFFFFFFu, p, off);
        if (lane == 0) g_style[b * 512 + i] = lrelu2(p * wmul + ab[i]);
    }
}

// ---------------- launch 1: wsq + U weight transform ----------------
__global__ void prep1_kernel(const float* __restrict__ cw) {
    if (blockIdx.x < 512) {
        int o = blockIdx.x, i = threadIdx.x;
        const float* p = cw + (size_t)o * 4608 + (size_t)i * 9;
        float s = 0.0f;
        #pragma unroll
        for (int t = 0; t < 9; t++) s += p[t] * p[t];
        g_wsq[o * 512 + i] = s;
        return;
    }
    int c8 = blockIdx.x - 512, o = threadIdx.x;
    #pragma unroll
    for (int k = 0; k < 8; k++) {
        int cin = c8 * 8 + kinv(k);
        const float* src = cw + (size_t)o * 4608 + (size_t)cin * 9;
        #pragma unroll
        for (int dy = 0; dy < 3; dy++) {
            float g0 = src[dy * 3 + 0], g1 = src[dy * 3 + 1], g2 = src[dy * 3 + 2];
            float u0 = g0;
            float u1 = (g0 + g1 + g2) * 0.5f;
            float u2 = (g0 - g1 + g2) * 0.5f;
            float u3 = g2;
            size_t base = ((((size_t)c8 * 4 + 0) * 3 + dy) * 512 + o) * 8 + k;
            size_t cstr = (size_t)3 * 512 * 8;
            g_wt[base + 0 * cstr] = f2tf32(u0);
            g_wt[base + 1 * cstr] = f2tf32(u1);
            g_wt[base + 2 * cstr] = f2tf32(u2);
            g_wt[base + 3 * cstr] = f2tf32(u3);
        }
    }
}

// ---------------- launch 2: V input transform + demod ----------------
__global__ void prep2_kernel(const float* __restrict__ x,
                             const float* __restrict__ noise,
                             const float* __restrict__ nw_p) {
    const int b = blockIdx.y;
    const int tid = threadIdx.x;

    if (blockIdx.x == 64) {
        __shared__ float s2[512];
        for (int i = tid; i < 512; i += 256) {
            float st = g_style[b * 512 + i];
            s2[i] = st * st;
        }
        __syncthreads();
        int lane = tid & 31, warp = tid >> 5;
        for (int n = 0; n < 64; n++) {
            int o = warp * 64 + n;
            const float* wr = g_wsq + (size_t)o * 512;
            float p = 0.0f;
            #pragma unroll 4
            for (int k = lane; k < 512; k += 32) p += wr[k] * s2[k];
            #pragma unroll
            for (int off = 16; off; off >>= 1) p += __shfl_xor_sync(0xFFFFFFFFu, p, off);
            if (lane == 0) g_demod[b * 512 + o] = rsqrtf(p + 1e-8f);
        }
        return;
    }

    const int c8 = blockIdx.x;
    __shared__ float xp[8][66];
    __shared__ float ns[64];
    __shared__ float sst[8];
    const float nw = *nw_p;
    if (tid < 8) sst[tid] = g_style[b * 512 + c8 * 8 + kinv(tid)];
    if (tid < 16) { int k = tid & 7; xp[k][(tid < 8) ? 0 : 65] = 0.0f; }

    const float* xb  = x + ((size_t)b * 512 + c8 * 8) * 4096;
    const float* nzb = noise + (size_t)b * 4096;
    float* outb = g_xm + ((size_t)b * 64 + c8) * (4 * 66 * 32 * 8);
    const size_t cplane = (size_t)66 * 32 * 8;

    for (int row = 0; row < 66; row++) {
        int h = row - 1;
        bool hin = (unsigned)h < 64u;
        __syncthreads();
        if (hin) {
            if (tid < 64) ns[tid] = nzb[h * 64 + tid];
            __syncthreads();
            #pragma unroll
            for (int j = tid; j < 512; j += 256) {
                int k = j >> 6, w = j & 63;
                float xv = xb[(size_t)kinv(k) * 4096 + h * 64 + w];
                xp[k][1 + w] = (xv + nw * ns[w]) * sst[k];
            }
        } else {
            #pragma unroll
            for (int j = tid; j < 512; j += 256) {
                int k = j >> 6, w = j & 63;
                xp[k][1 + w] = 0.0f;
            }
        }
        __syncthreads();
        int pc = tid >> 3, k = tid & 7;
        float d0 = xp[k][2 * pc + 0];
        float d1 = xp[k][2 * pc + 1];
        float d2 = xp[k][2 * pc + 2];
        float d3 = xp[k][2 * pc + 3];
        float* orow = outb + (size_t)row * 256 + tid;
        orow[0 * cplane] = f2tf32(d0 - d2);
        orow[1 * cplane] = f2tf32(d1 + d2);
        orow[2 * cplane] = f2tf32(d2 - d1);
        orow[3 * cplane] = f2tf32(d1 - d3);
    }
}

// ---------------- launch 3: conv — Winograd F(2,3)-width, tf32 mma.sync ----------------
// CTA: 64 cout x 256 pixels (4 output rows = 128 pairs), 512 threads / 16 warps.
// Warp: 16 cout x 128 pairs, one component (wc = warp & 3, wm = (warp>>2)*16).
// Stage floats: Us [comp4][dy3][o64][k8] = 6144, Vs [comp4][row6][pair32][k8] = 6144. STAGEF = 12288.
#define STAGEF 12288
#define VS_OFF 6144
#define EPL 130
#define CPLN (64 * EPL)       // 8320 floats per comp plane
#define SMEMF 36864           // max(3*STAGEF, 4*CPLN) = 36864 floats = 147456 B

#define WAITG(n) asm volatile("cp.async.wait_group %0;\n" :: "n"(n))
#define COMMIT() asm volatile("cp.async.commit_group;\n")

__global__ __launch_bounds__(512, 1)
void conv_kernel(const float* __restrict__ bias, float* __restrict__ out) {
    extern __shared__ float smem[];

    const int b  = blockIdx.z;
    const int o0 = blockIdx.y * 64;
    const int pt = blockIdx.x;
    const int h0 = pt * 4;                 // first output row (== first V row index)
    const int tid = threadIdx.x;
    const int lane = tid & 31, warp = tid >> 5;
    const int wm = (warp >> 2) * 16;       // cout offset: 0,16,32,48
    const int wc = warp & 3;               // Winograd component
    const int g = lane >> 2, t = lane & 3;

    // per-thread fill source pointers (advance by constant stride per chunk)
    const int i0 = tid, i1 = tid + 512, i2 = tid + 1024;   // < 1536
    const float* uS0 = g_wt + (i0 >> 7) * 4096 + o0 * 8 + (i0 & 127) * 4;
    const float* uS1 = g_wt + (i1 >> 7) * 4096 + o0 * 8 + (i1 & 127) * 4;
    const float* uS2 = g_wt + (i2 >> 7) * 4096 + o0 * 8 + (i2 & 127) * 4;
    const float* vB = g_xm + ((size_t)b * 64) * (4 * 66 * 32 * 8) + (size_t)h0 * 256;
    const float* vS0 = vB + (i0 / 384) * (66 * 256) + (i0 % 384) * 4;
    const float* vS1 = vB + (i1 / 384) * (66 * 256) + (i1 % 384) * 4;
    const float* vS2 = vB + (i2 / 384) * (66 * 256) + (i2 % 384) * 4;
    // dst offsets (per stage add slot*STAGEF)
    const unsigned uD0 = smem_u32(smem + (i0 >> 7) * 512 + (i0 & 127) * 4);
    const unsigned uD1 = smem_u32(smem + (i1 >> 7) * 512 + (i1 & 127) * 4);
    const unsigned uD2 = smem_u32(smem + (i2 >> 7) * 512 + (i2 & 127) * 4);
    const unsigned vD0 = smem_u32(smem + VS_OFF + i0 * 4);
    const unsigned vD1 = smem_u32(smem + VS_OFF + i1 * 4);
    const unsigned vD2 = smem_u32(smem + VS_OFF + i2 * 4);

    float d[16][4];
    #pragma unroll
    for (int nf = 0; nf < 16; nf++)
        #pragma unroll
        for (int j = 0; j < 4; j++) d[nf][j] = 0.0f;

    auto fillAt = [&](int slot) {
        const unsigned so = slot * STAGEF * 4u;
        cp16(uD0 + so, uS0); cp16(uD1 + so, uS1); cp16(uD2 + so, uS2);
        cp16(vD0 + so, vS0); cp16(vD1 + so, vS1); cp16(vD2 + so, vS2);
        uS0 += 49152; uS1 += 49152; uS2 += 49152;
        vS0 += 67584; vS1 += 67584; vS2 += 67584;
    };

    auto compute = [&](int slot) {
        const float* sU = smem + slot * STAGEF;
        const float* sV = sU + VS_OFF + wc * 1536 + g * 8 + 2 * t;
        // A fragments for 3 dy
        float2 A0[3], A1[3];
        #pragma unroll
        for (int dy = 0; dy < 3; dy++) {
            const float* slab = sU + (wc * 3 + dy) * 512;
            A0[dy] = *reinterpret_cast<const float2*>(slab + (wm + g) * 8 + 2 * t);
            A1[dy] = *reinterpret_cast<const float2*>(slab + (wm + 8 + g) * 8 + 2 * t);
        }
        // B sliding window: rows or..or+2, ring slot r%3, [pairgrp 4]
        float2 Br[3][4];
        #pragma unroll
        for (int r = 0; r < 3; r++)
            #pragma unroll
            for (int pg = 0; pg < 4; pg++)
                Br[r][pg] = *reinterpret_cast<const float2*>(sV + (r * 32 + pg * 8) * 8);
        #pragma unroll
        for (int orow = 0; orow < 4; orow++) {
            #pragma unroll
            for (int dy = 0; dy < 3; dy++) {
                int r = (orow + dy) % 3;
                #pragma unroll
                for (int pg = 0; pg < 4; pg++)
                    mma_tf32(d[orow * 4 + pg],
                             A0[dy].x, A1[dy].x, A0[dy].y, A1[dy].y,
                             Br[r][pg].x, Br[r][pg].y);
            }
            if (orow < 3) {
                int nr = orow + 3;
                #pragma unroll
                for (int pg = 0; pg < 4; pg++)
                    Br[orow % 3][pg] = *reinterpret_cast<const float2*>(sV + (nr * 32 + pg * 8) * 8);
            }
        }
    };

    fillAt(0); COMMIT();
    fillAt(1); COMMIT();

    auto step = [&](int c, int slot) {
        WAITG(1);
        __syncthreads();
        if (c + 2 < 64) fillAt((slot + 2) % 3);
        COMMIT();
        compute(slot);
    };

    #pragma unroll 1
    for (int cc = 0; cc < 63; cc += 3) {
        step(cc + 0, 0);
        step(cc + 1, 1);
        step(cc + 2, 2);
    }
    step(63, 0);

    WAITG(0);
    __syncthreads();

    // ---- epilogue phase 1: dump m-planes [comp][m64][pair128 stride EPL] ----
    #pragma unroll
    for (int nf = 0; nf < 16; nf++) {
        int pr = nf * 8 + 2 * t;
        float* p0 = smem + wc * CPLN + (wm + g) * EPL + pr;
        float* p1 = p0 + 8 * EPL;
        p0[0] = d[nf][0]; p0[1] = d[nf][1];
        p1[0] = d[nf][2]; p1[1] = d[nf][3];
    }
    __syncthreads();

    // ---- epilogue phase 2: y0 = m0+m1+m2, y1 = m1-m2-m3; demod/bias/lrelu; store ----
    const float* dm = g_demod + b * 512;
    #pragma unroll
    for (int it = 0; it < 16; it++) {
        int idx = it * 512 + tid;          // (m, pair): 64 x 128
        int m = idx >> 7, pair = idx & 127;
        const float* pm = smem + m * EPL + pair;
        float m0 = pm[0 * CPLN];
        float m1 = pm[1 * CPLN];
        float m2 = pm[2 * CPLN];
        float m3 = pm[3 * CPLN];
        int o = o0 + m;
        float dem = dm[o], bv = bias[o];
        float2 v;
        v.x = lrelu2((m0 + m1 + m2) * dem + bv);
        v.y = lrelu2((m1 - m2 - m3) * dem + bv);
        int row = h0 + (pair >> 5);
        int col = (pair & 31) * 2;
        *reinterpret_cast<float2*>(out + ((size_t)b * 512 + o) * 4096 + row * 64 + col) = v;
    }
}

// ---------------- launch ----------------
extern "C" void kernel_launch(void* const* d_in, const int* in_sizes, int n_in,
                              void* d_out, int out_size) {
    const float* x      = (const float*)d_in[0];
    const float* latent = (const float*)d_in[1];
    const float* noise  = (const float*)d_in[2];
    const float* aw     = (const float*)d_in[3];
    const float* ab     = (const float*)d_in[4];
    const float* cw     = (const float*)d_in[5];
    const float* nw     = (const float*)d_in[6];
    const float* bias   = (const float*)d_in[7];
    float* out = (float*)d_out;

    cudaFuncSetAttribute(conv_kernel, cudaFuncAttributeMaxDynamicSharedMemorySize,
                         SMEMF * (int)sizeof(float));

    style_kernel<<<16, 512>>>(latent, aw, ab);
    prep1_kernel<<<576, 512>>>(cw);
    prep2_kernel<<<dim3(65, 16), 256>>>(x, noise, nw);
    conv_kernel<<<dim3(16, 8, 16), 512, SMEMF * sizeof(float)>>>(bias, out);
}

// round 16
// speedup vs baseline: 1.2569x; 1.0454x over previous
#include <cuda_runtime.h>
#include <cuda_bf16.h>
#include <cstdint>

#define SQRT2F 1.41421356237309515f

// ---------------- scratch (allocation-free: __device__ globals) ----------------
__device__ float g_style[16 * 512];
__device__ float g_demod[16 * 512];
__device__ float g_wsq[512 * 512];
// U: [c8][comp4][dy3][o512][k8]  (tf32)
__device__ float g_wt[64 * 4 * 3 * 512 * 8];
// V: [b][c8][comp4][row66][pair32][k8]   (tf32)
__device__ float g_xm[(size_t)16 * 64 * 4 * 66 * 32 * 8];

__device__ __forceinline__ int kinv(int p) { return (p >> 1) + ((p & 1) << 2); }

__device__ __forceinline__ float f2tf32(float f) {
    unsigned r;
    asm("cvt.rna.tf32.f32 %0, %1;" : "=r"(r) : "f"(f));
    return __uint_as_float(r);
}

__device__ __forceinline__ void mma_tf32(float d[4],
                                         float a0, float a1, float a2, float a3,
                                         float b0, float b1) {
    asm volatile(
        "mma.sync.aligned.m16n8k8.row.col.f32.tf32.tf32.f32 "
        "{%0,%1,%2,%3}, {%4,%5,%6,%7}, {%8,%9}, {%0,%1,%2,%3};"
        : "+f"(d[0]), "+f"(d[1]), "+f"(d[2]), "+f"(d[3])
        : "r"(__float_as_uint(a0)), "r"(__float_as_uint(a1)),
          "r"(__float_as_uint(a2)), "r"(__float_as_uint(a3)),
          "r"(__float_as_uint(b0)), "r"(__float_as_uint(b1)));
}

__device__ __forceinline__ float lrelu2(float v) {
    return (v > 0.0f ? v : 0.2f * v) * SQRT2F;
}

__device__ __forceinline__ unsigned smem_u32(const void* p) {
    return (unsigned)__cvta_generic_to_shared(p);
}
__device__ __forceinline__ void cp16(unsigned dst, const void* src) {
    asm volatile("cp.async.cg.shared.global [%0], [%1], 16;\n" :: "r"(dst), "l"(src));
}
#define WAITG(n) asm volatile("cp.async.wait_group %0;\n" :: "n"(n))
#define COMMIT() asm volatile("cp.async.commit_group;\n")

// ---------------- launch 0: style (fp32 exact) ----------------
__global__ void style_kernel(const float* __restrict__ latent,
                             const float* __restrict__ aw,
                             const float* __restrict__ ab) {
    int b = blockIdx.x;
    int tid = threadIdx.x, lane = tid & 31, warp = tid >> 5;
    __shared__ float lat[512];
    lat[tid] = latent[b * 512 + tid];
    __syncthreads();
    const float wmul = rsqrtf(512.0f);
    for (int n = 0; n < 32; n++) {
        int i = warp * 32 + n;
        const float* wr = aw + (size_t)i * 512;
        float p = 0.0f;
        #pragma unroll 4
        for (int k = lane; k < 512; k += 32) p += wr[k] * lat[k];
        #pragma unroll
        for (int off = 16; off; off >>= 1) p += __shfl_xor_sync(0xFFFFFFFFu, p, off);
        if (lane == 0) g_style[b * 512 + i] = lrelu2(p * wmul + ab[i]);
    }
}

// ---------------- launch 1: wsq + U weight transform ----------------
__global__ void prep1_kernel(const float* __restrict__ cw) {
    if (blockIdx.x < 512) {
        int o = blockIdx.x, i = threadIdx.x;
        const float* p = cw + (size_t)o * 4608 + (size_t)i * 9;
        float s = 0.0f;
        #pragma unroll
        for (int t = 0; t < 9; t++) s += p[t] * p[t];
        g_wsq[o * 512 + i] = s;
        return;
    }
    int c8 = blockIdx.x - 512, o = threadIdx.x;
    #pragma unroll
    for (int k = 0; k < 8; k++) {
        int cin = c8 * 8 + kinv(k);
        const float* src = cw + (size_t)o * 4608 + (size_t)cin * 9;
        #pragma unroll
        for (int dy = 0; dy < 3; dy++) {
            float g0 = src[dy * 3 + 0], g1 = src[dy * 3 + 1], g2 = src[dy * 3 + 2];
            float u0 = g0;
            float u1 = (g0 + g1 + g2) * 0.5f;
            float u2 = (g0 - g1 + g2) * 0.5f;
            float u3 = g2;
            size_t base = ((((size_t)c8 * 4 + 0) * 3 + dy) * 512 + o) * 8 + k;
            size_t cstr = (size_t)3 * 512 * 8;
            g_wt[base + 0 * cstr] = f2tf32(u0);
            g_wt[base + 1 * cstr] = f2tf32(u1);
            g_wt[base + 2 * cstr] = f2tf32(u2);
            g_wt[base + 3 * cstr] = f2tf32(u3);
        }
    }
}

// ---------------- launch 2: V input transform + demod ----------------
__global__ void prep2_kernel(const float* __restrict__ x,
                             const float* __restrict__ noise,
                             const float* __restrict__ nw_p) {
    const int b = blockIdx.y;
    const int tid = threadIdx.x;

    if (blockIdx.x == 64) {
        __shared__ float s2[512];
        for (int i = tid; i < 512; i += 256) {
            float st = g_style[b * 512 + i];
            s2[i] = st * st;
        }
        __syncthreads();
        int lane = tid & 31, warp = tid >> 5;
        for (int n = 0; n < 64; n++) {
            int o = warp * 64 + n;
            const float* wr = g_wsq + (size_t)o * 512;
            float p = 0.0f;
            #pragma unroll 4
            for (int k = lane; k < 512; k += 32) p += wr[k] * s2[k];
            #pragma unroll
            for (int off = 16; off; off >>= 1) p += __shfl_xor_sync(0xFFFFFFFFu, p, off);
            if (lane == 0) g_demod[b * 512 + o] = rsqrtf(p + 1e-8f);
        }
        return;
    }

    const int c8 = blockIdx.x;
    __shared__ float xp[8][66];
    __shared__ float ns[64];
    __shared__ float sst[8];
    const float nw = *nw_p;
    if (tid < 8) sst[tid] = g_style[b * 512 + c8 * 8 + kinv(tid)];
    if (tid < 16) { int k = tid & 7; xp[k][(tid < 8) ? 0 : 65] = 0.0f; }

    const float* xb  = x + ((size_t)b * 512 + c8 * 8) * 4096;
    const float* nzb = noise + (size_t)b * 4096;
    float* outb = g_xm + ((size_t)b * 64 + c8) * (4 * 66 * 32 * 8);
    const size_t cplane = (size_t)66 * 32 * 8;

    for (int row = 0; row < 66; row++) {
        int h = row - 1;
        bool hin = (unsigned)h < 64u;
        __syncthreads();
        if (hin) {
            if (tid < 64) ns[tid] = nzb[h * 64 + tid];
            __syncthreads();
            #pragma unroll
            for (int j = tid; j < 512; j += 256) {
                int k = j >> 6, w = j & 63;
                float xv = xb[(size_t)kinv(k) * 4096 + h * 64 + w];
                xp[k][1 + w] = (xv + nw * ns[w]) * sst[k];
            }
        } else {
            #pragma unroll
            for (int j = tid; j < 512; j += 256) {
                int k = j >> 6, w = j & 63;
                xp[k][1 + w] = 0.0f;
            }
        }
        __syncthreads();
        int pc = tid >> 3, k = tid & 7;
        float d0 = xp[k][2 * pc + 0];
        float d1 = xp[k][2 * pc + 1];
        float d2 = xp[k][2 * pc + 2];
        float d3 = xp[k][2 * pc + 3];
        float* orow = outb + (size_t)row * 256 + tid;
        orow[0 * cplane] = f2tf32(d0 - d2);
        orow[1 * cplane] = f2tf32(d1 + d2);
        orow[2 * cplane] = f2tf32(d2 - d1);
        orow[3 * cplane] = f2tf32(d1 - d3);
    }
}

// ---------------- launch 3: conv — Winograd F(2,3)-width, tf32 mma.sync, 2 CTAs/SM ----------------
// CTA: 64 cout x 128 pixels (2 output rows = 64 pairs), 256 threads / 8 warps, 2 CTAs per SM.
// Warp: 32 cout x 64 pairs, one component (wc = warp & 3, wm = (warp>>2)*32).
// Stage floats: Us [comp4][dy3][o64][k8] = 6144, Vs [comp4][row4][pair32][k8] = 4096. STG = 10240.
#define STG 10240
#define VOF 6144
#define EPL2 66
#define CPLN2 (64 * EPL2)     // 4224 floats per comp plane
#define SMEMF2 20480          // 2*STG floats = 81920 B (>= 4*CPLN2 = 16896)

__global__ __launch_bounds__(256, 2)
void conv_kernel(const float* __restrict__ bias, float* __restrict__ out) {
    extern __shared__ float smem[];

    const int b  = blockIdx.z;
    const int o0 = blockIdx.y * 64;
    const int pt = blockIdx.x;
    const int h0 = pt * 2;                 // first output row (== first V row of 4-row window)
    const int tid = threadIdx.x;
    const int lane = tid & 31, warp = tid >> 5;
    const int wm = (warp >> 2) * 32;       // cout offset: 0 or 32
    const int wc = warp & 3;               // Winograd component
    const int g = lane >> 2, t = lane & 3;

    // fill addressing: U 6 float4/thread, V 4 float4/thread
    const int t127 = tid & 127, hi = tid >> 7;
    const float* uS = g_wt + (size_t)o0 * 8 + hi * 4096 + t127 * 4;              // +r*8192
    const float* vS = g_xm + ((size_t)b * 64) * (4 * 66 * 256) + h0 * 256 + tid * 4; // +r*16896
    const unsigned uD = smem_u32(smem + hi * 512 + t127 * 4);                    // +r*4096B
    const unsigned vD = smem_u32(smem + VOF + tid * 4);                          // +r*4096B

    float d[16][4];   // [mf2][orow2][pg4]
    #pragma unroll
    for (int nf = 0; nf < 16; nf++)
        #pragma unroll
        for (int j = 0; j < 4; j++) d[nf][j] = 0.0f;

    auto fillAt = [&](int slot) {
        const unsigned so = (unsigned)slot * (STG * 4u);
        #pragma unroll
        for (int r = 0; r < 6; r++) cp16(uD + so + r * 4096u, uS + r * 8192);
        #pragma unroll
        for (int r = 0; r < 4; r++) cp16(vD + so + r * 4096u, vS + r * 16896);
        uS += 49152;   // 12 slabs x 4096 floats per c8
        vS += 67584;   // 4 comps x 66*256 floats per c8
    };

    auto compute = [&](int slot) {
        const float* sU = smem + slot * STG;
        const float* sV = sU + VOF + wc * 1024 + g * 8 + 2 * t;
        // B window: all 4 rows x 4 pair-groups
        float2 Br[4][4];
        #pragma unroll
        for (int r = 0; r < 4; r++)
            #pragma unroll
            for (int pg = 0; pg < 4; pg++)
                Br[r][pg] = *reinterpret_cast<const float2*>(sV + (r * 32 + pg * 8) * 8);
        #pragma unroll
        for (int dy = 0; dy < 3; dy++) {
            const float* slab = sU + (wc * 3 + dy) * 512 + 2 * t;
            float2 A0 = *reinterpret_cast<const float2*>(slab + (wm + g) * 8);
            float2 A1 = *reinterpret_cast<const float2*>(slab + (wm + 8 + g) * 8);
            float2 A2 = *reinterpret_cast<const float2*>(slab + (wm + 16 + g) * 8);
            float2 A3 = *reinterpret_cast<const float2*>(slab + (wm + 24 + g) * 8);
            #pragma unroll
            for (int orow = 0; orow < 2; orow++) {
                int r = orow + dy;
                #pragma unroll
                for (int pg = 0; pg < 4; pg++) {
                    mma_tf32(d[orow * 4 + pg], A0.x, A1.x, A0.y, A1.y,
                             Br[r][pg].x, Br[r][pg].y);
                    mma_tf32(d[8 + orow * 4 + pg], A2.x, A3.x, A2.y, A3.y,
                             Br[r][pg].x, Br[r][pg].y);
                }
            }
        }
    };

    fillAt(0); COMMIT();
    fillAt(1); COMMIT();

    for (int c = 0; c < 64; c++) {
        WAITG(1);
        __syncthreads();
        compute(c & 1);
        __syncthreads();
        if (c + 2 < 64) { fillAt(c & 1); }
        COMMIT();
    }
    WAITG(0);
    __syncthreads();

    // ---- epilogue phase 1: dump m-planes [comp][m64][pair64 stride EPL2] ----
    #pragma unroll
    for (int mf = 0; mf < 2; mf++) {
        #pragma unroll
        for (int orow = 0; orow < 2; orow++) {
            #pragma unroll
            for (int pg = 0; pg < 4; pg++) {
                const float* dd = d[mf * 8 + orow * 4 + pg];
                int m0 = wm + mf * 16 + g;
                int pr = orow * 32 + pg * 8 + 2 * t;
                float* p0 = smem + wc * CPLN2 + m0 * EPL2 + pr;
                float* p1 = p0 + 8 * EPL2;
                p0[0] = dd[0]; p0[1] = dd[1];
                p1[0] = dd[2]; p1[1] = dd[3];
            }
        }
    }
    __syncthreads();

    // ---- epilogue phase 2: y0 = m0+m1+m2, y1 = m1-m2-m3; demod/bias/lrelu; store ----
    const float* dm = g_demod + b * 512;
    #pragma unroll
    for (int it = 0; it < 16; it++) {
        int idx = it * 256 + tid;          // (m, pair): 64 x 64
        int m = idx >> 6, pair = idx & 63;
        const float* pm = smem + m * EPL2 + pair;
        float m0 = pm[0 * CPLN2];
        float m1 = pm[1 * CPLN2];
        float m2 = pm[2 * CPLN2];
        float m3 = pm[3 * CPLN2];
        int o = o0 + m;
        float dem = dm[o], bv = bias[o];
        float2 v;
        v.x = lrelu2((m0 + m1 + m2) * dem + bv);
        v.y = lrelu2((m1 - m2 - m3) * dem + bv);
        int row = h0 + (pair >> 5);
        int col = (pair & 31) * 2;
        *reinterpret_cast<float2*>(out + ((size_t)b * 512 + o) * 4096 + row * 64 + col) = v;
    }
}

// ---------------- launch ----------------
extern "C" void kernel_launch(void* const* d_in, const int* in_sizes, int n_in,
                              void* d_out, int out_size) {
    const float* x      = (const float*)d_in[0];
    const float* latent = (const float*)d_in[1];
    const float* noise  = (const float*)d_in[2];
    const float* aw     = (const float*)d_in[3];
    const float* ab     = (const float*)d_in[4];
    const float* cw     = (const float*)d_in[5];
    const float* nw     = (const float*)d_in[6];
    const float* bias   = (const float*)d_in[7];
    float* out = (float*)d_out;

    cudaFuncSetAttribute(conv_kernel, cudaFuncAttributeMaxDynamicSharedMemorySize,
                         SMEMF2 * (int)sizeof(float));

    style_kernel<<<16, 512>>>(latent, aw, ab);
    prep1_kernel<<<576, 512>>>(cw);
    prep2_kernel<<<dim3(65, 16), 256>>>(x, noise, nw);
    conv_kernel<<<dim3(32, 8, 16), 256, SMEMF2 * sizeof(float)>>>(bias, out);
}

// round 17
// speedup vs baseline: 1.2858x; 1.0230x over previous
#include <cuda_runtime.h>
#include <cuda_bf16.h>
#include <cstdint>

#define SQRT2F 1.41421356237309515f

// ---------------- scratch (allocation-free: __device__ globals) ----------------
__device__ float g_style[16 * 512];
__device__ float g_demod[16 * 512];
__device__ float g_wsq[512 * 512];
// U: [c8][comp4][dy3][o512][k8]  (tf32)
__device__ float g_wt[64 * 4 * 3 * 512 * 8];
// V: [b][c8][comp4][row66][pair32][k8]   (tf32)
__device__ float g_xm[(size_t)16 * 64 * 4 * 66 * 32 * 8];

__device__ __forceinline__ int kinv(int p) { return (p >> 1) + ((p & 1) << 2); }

__device__ __forceinline__ float f2tf32(float f) {
    unsigned r;
    asm("cvt.rna.tf32.f32 %0, %1;" : "=r"(r) : "f"(f));
    return __uint_as_float(r);
}

__device__ __forceinline__ void mma_tf32(float d[4],
                                         float a0, float a1, float a2, float a3,
                                         float b0, float b1) {
    asm volatile(
        "mma.sync.aligned.m16n8k8.row.col.f32.tf32.tf32.f32 "
        "{%0,%1,%2,%3}, {%4,%5,%6,%7}, {%8,%9}, {%0,%1,%2,%3};"
        : "+f"(d[0]), "+f"(d[1]), "+f"(d[2]), "+f"(d[3])
        : "r"(__float_as_uint(a0)), "r"(__float_as_uint(a1)),
          "r"(__float_as_uint(a2)), "r"(__float_as_uint(a3)),
          "r"(__float_as_uint(b0)), "r"(__float_as_uint(b1)));
}

__device__ __forceinline__ float lrelu2(float v) {
    return (v > 0.0f ? v : 0.2f * v) * SQRT2F;
}

__device__ __forceinline__ unsigned smem_u32(const void* p) {
    return (unsigned)__cvta_generic_to_shared(p);
}
__device__ __forceinline__ void cp16(unsigned dst, const void* src) {
    asm volatile("cp.async.cg.shared.global [%0], [%1], 16;\n" :: "r"(dst), "l"(src));
}
#define WAITG(n) asm volatile("cp.async.wait_group %0;\n" :: "n"(n))
#define COMMIT() asm volatile("cp.async.commit_group;\n")

// ---------------- launch 0: style (fp32 exact) ----------------
__global__ void style_kernel(const float* __restrict__ latent,
                             const float* __restrict__ aw,
                             const float* __restrict__ ab) {
    int b = blockIdx.x;
    int tid = threadIdx.x, lane = tid & 31, warp = tid >> 5;
    __shared__ float lat[512];
    lat[tid] = latent[b * 512 + tid];
    __syncthreads();
    const float wmul = rsqrtf(512.0f);
    for (int n = 0; n < 32; n++) {
        int i = warp * 32 + n;
        const float* wr = aw + (size_t)i * 512;
        float p = 0.0f;
        #pragma unroll 4
        for (int k = lane; k < 512; k += 32) p += wr[k] * lat[k];
        #pragma unroll
        for (int off = 16; off; off >>= 1) p += __shfl_xor_sync(0xFFFFFFFFu, p, off);
        if (lane == 0) g_style[b * 512 + i] = lrelu2(p * wmul + ab[i]);
    }
}

// ---------------- launch 1: wsq + U weight transform ----------------
__global__ void prep1_kernel(const float* __restrict__ cw) {
    if (blockIdx.x < 512) {
        int o = blockIdx.x, i = threadIdx.x;
        const float* p = cw + (size_t)o * 4608 + (size_t)i * 9;
        float s = 0.0f;
        #pragma unroll
        for (int t = 0; t < 9; t++) s += p[t] * p[t];
        g_wsq[o * 512 + i] = s;
        return;
    }
    int c8 = blockIdx.x - 512, o = threadIdx.x;
    #pragma unroll
    for (int k = 0; k < 8; k++) {
        int cin = c8 * 8 + kinv(k);
        const float* src = cw + (size_t)o * 4608 + (size_t)cin * 9;
        #pragma unroll
        for (int dy = 0; dy < 3; dy++) {
            float g0 = src[dy * 3 + 0], g1 = src[dy * 3 + 1], g2 = src[dy * 3 + 2];
            float u0 = g0;
            float u1 = (g0 + g1 + g2) * 0.5f;
            float u2 = (g0 - g1 + g2) * 0.5f;
            float u3 = g2;
            size_t base = ((((size_t)c8 * 4 + 0) * 3 + dy) * 512 + o) * 8 + k;
            size_t cstr = (size_t)3 * 512 * 8;
            g_wt[base + 0 * cstr] = f2tf32(u0);
            g_wt[base + 1 * cstr] = f2tf32(u1);
            g_wt[base + 2 * cstr] = f2tf32(u2);
            g_wt[base + 3 * cstr] = f2tf32(u3);
        }
    }
}

// ---------------- launch 2: V input transform (row-parallel, 1 warp/row) + demod ----------------
__global__ void prep2_kernel(const float* __restrict__ x,
                             const float* __restrict__ noise,
                             const float* __restrict__ nw_p) {
    const int b = blockIdx.y;
    const int tid = threadIdx.x;

    if (blockIdx.x == 64) {
        // demod[b,o] = rsqrt(sum_i wsq[o,i]*style[b,i]^2 + 1e-8)
        __shared__ float s2[512];
        for (int i = tid; i < 512; i += 256) {
            float st = g_style[b * 512 + i];
            s2[i] = st * st;
        }
        __syncthreads();
        int lane = tid & 31, warp = tid >> 5;
        for (int n = 0; n < 64; n++) {
            int o = warp * 64 + n;
            const float* wr = g_wsq + (size_t)o * 512;
            float p = 0.0f;
            #pragma unroll 4
            for (int k = lane; k < 512; k += 32) p += wr[k] * s2[k];
            #pragma unroll
            for (int off = 16; off; off >>= 1) p += __shfl_xor_sync(0xFFFFFFFFu, p, off);
            if (lane == 0) g_demod[b * 512 + o] = rsqrtf(p + 1e-8f);
        }
        return;
    }

    // V-prep for (b, c8): one warp per row, no block barriers.
    const int c8 = blockIdx.x;
    const int lane = tid & 31, wid = tid >> 5;
    __shared__ float xs[8][8][68];   // [warp][k][w+1 halo]
    const float nw = *nw_p;
    float st[8];
    #pragma unroll
    for (int k = 0; k < 8; k++) st[k] = g_style[b * 512 + c8 * 8 + kinv(k)];

    const float* xb  = x + ((size_t)b * 512 + c8 * 8) * 4096;
    const float* nzb = noise + (size_t)b * 4096;
    float* outb = g_xm + ((size_t)b * 64 + c8) * (4 * 66 * 256);
    const size_t cplane = (size_t)66 * 256;

    for (int row = wid; row < 66; row += 8) {
        int h = row - 1;
        float* orow = outb + (size_t)row * 256;
        if ((unsigned)h < 64u) {
            // load + modulate into warp-private slab (coalesced reads)
            #pragma unroll
            for (int it = 0; it < 16; it++) {
                int j = lane + it * 32;
                int k = j >> 6, w = j & 63;
                float xv = xb[(size_t)kinv(k) * 4096 + h * 64 + w];
                xs[wid][k][w + 1] = (xv + nw * nzb[h * 64 + w]) * st[k];
            }
            if (lane < 8) { xs[wid][lane][0] = 0.0f; xs[wid][lane][65] = 0.0f; }
            __syncwarp();
            // transform + coalesced store: j = pc*8 + k contiguous over lanes
            #pragma unroll
            for (int it = 0; it < 8; it++) {
                int j = lane + it * 32;
                int pc = j >> 3, k = j & 7;
                float d0 = xs[wid][k][2 * pc + 0];
                float d1 = xs[wid][k][2 * pc + 1];
                float d2 = xs[wid][k][2 * pc + 2];
                float d3 = xs[wid][k][2 * pc + 3];
                orow[0 * cplane + j] = f2tf32(d0 - d2);
                orow[1 * cplane + j] = f2tf32(d1 + d2);
                orow[2 * cplane + j] = f2tf32(d2 - d1);
                orow[3 * cplane + j] = f2tf32(d1 - d3);
            }
            __syncwarp();
        } else {
            #pragma unroll
            for (int it = 0; it < 8; it++) {
                int j = lane + it * 32;
                orow[0 * cplane + j] = 0.0f;
                orow[1 * cplane + j] = 0.0f;
                orow[2 * cplane + j] = 0.0f;
                orow[3 * cplane + j] = 0.0f;
            }
        }
    }
}

// ---------------- launch 3: conv — Winograd F(2,3)-width, tf32 mma.sync, 2 CTAs/SM ----------------
// CTA: 64 cout x 128 pixels (2 output rows = 64 pairs), 256 threads / 8 warps, 2 CTAs per SM.
// Warp: 32 cout x 64 pairs, one component (wc = warp & 3, wm = (warp>>2)*32).
// Stage floats: Us [comp4][dy3][o64][k8] = 6144, Vs [comp4][row4][pair32][k8] = 4096. STG = 10240.
#define STG 10240
#define VOF 6144
#define EPL2 66
#define CPLN2 (64 * EPL2)     // 4224 floats per comp plane
#define SMEMF2 20480          // 2*STG floats = 81920 B (>= 4*CPLN2 = 16896)

__global__ __launch_bounds__(256, 2)
void conv_kernel(const float* __restrict__ bias, float* __restrict__ out) {
    extern __shared__ float smem[];

    const int b  = blockIdx.z;
    const int o0 = blockIdx.y * 64;
    const int pt = blockIdx.x;
    const int h0 = pt * 2;
    const int tid = threadIdx.x;
    const int lane = tid & 31, warp = tid >> 5;
    const int wm = (warp >> 2) * 32;
    const int wc = warp & 3;
    const int g = lane >> 2, t = lane & 3;

    const int t127 = tid & 127, hi = tid >> 7;
    const float* uS = g_wt + (size_t)o0 * 8 + hi * 4096 + t127 * 4;
    const float* vS = g_xm + ((size_t)b * 64) * (4 * 66 * 256) + h0 * 256 + tid * 4;
    const unsigned uD = smem_u32(smem + hi * 512 + t127 * 4);
    const unsigned vD = smem_u32(smem + VOF + tid * 4);

    float d[16][4];
    #pragma unroll
    for (int nf = 0; nf < 16; nf++)
        #pragma unroll
        for (int j = 0; j < 4; j++) d[nf][j] = 0.0f;

    auto fillAt = [&](int slot) {
        const unsigned so = (unsigned)slot * (STG * 4u);
        #pragma unroll
        for (int r = 0; r < 6; r++) cp16(uD + so + r * 4096u, uS + r * 8192);
        #pragma unroll
        for (int r = 0; r < 4; r++) cp16(vD + so + r * 4096u, vS + r * 16896);
        uS += 49152;
        vS += 67584;
    };

    auto compute = [&](int slot) {
        const float* sU = smem + slot * STG;
        const float* sV = sU + VOF + wc * 1024 + g * 8 + 2 * t;
        float2 Br[4][4];
        #pragma unroll
        for (int r = 0; r < 4; r++)
            #pragma unroll
            for (int pg = 0; pg < 4; pg++)
                Br[r][pg] = *reinterpret_cast<const float2*>(sV + (r * 32 + pg * 8) * 8);
        #pragma unroll
        for (int dy = 0; dy < 3; dy++) {
            const float* slab = sU + (wc * 3 + dy) * 512 + 2 * t;
            float2 A0 = *reinterpret_cast<const float2*>(slab + (wm + g) * 8);
            float2 A1 = *reinterpret_cast<const float2*>(slab + (wm + 8 + g) * 8);
            float2 A2 = *reinterpret_cast<const float2*>(slab + (wm + 16 + g) * 8);
            float2 A3 = *reinterpret_cast<const float2*>(slab + (wm + 24 + g) * 8);
            #pragma unroll
            for (int orow = 0; orow < 2; orow++) {
                int r = orow + dy;
                #pragma unroll
                for (int pg = 0; pg < 4; pg++) {
                    mma_tf32(d[orow * 4 + pg], A0.x, A1.x, A0.y, A1.y,
                             Br[r][pg].x, Br[r][pg].y);
                    mma_tf32(d[8 + orow * 4 + pg], A2.x, A3.x, A2.y, A3.y,
                             Br[r][pg].x, Br[r][pg].y);
                }
            }
        }
    };

    fillAt(0); COMMIT();
    fillAt(1); COMMIT();

    #pragma unroll 2
    for (int c = 0; c < 64; c++) {
        WAITG(1);
        __syncthreads();
        compute(c & 1);
        __syncthreads();
        if (c + 2 < 64) { fillAt(c & 1); }
        COMMIT();
    }
    WAITG(0);
    __syncthreads();

    // ---- epilogue phase 1: dump m-planes [comp][m64][pair64 stride EPL2] ----
    #pragma unroll
    for (int mf = 0; mf < 2; mf++) {
        #pragma unroll
        for (int orow = 0; orow < 2; orow++) {
            #pragma unroll
            for (int pg = 0; pg < 4; pg++) {
                const float* dd = d[mf * 8 + orow * 4 + pg];
                int m0 = wm + mf * 16 + g;
                int pr = orow * 32 + pg * 8 + 2 * t;
                float* p0 = smem + wc * CPLN2 + m0 * EPL2 + pr;
                float* p1 = p0 + 8 * EPL2;
                p0[0] = dd[0]; p0[1] = dd[1];
                p1[0] = dd[2]; p1[1] = dd[3];
            }
        }
    }
    __syncthreads();

    // ---- epilogue phase 2: y0 = m0+m1+m2, y1 = m1-m2-m3; demod/bias/lrelu; store ----
    const float* dm = g_demod + b * 512;
    #pragma unroll
    for (int it = 0; it < 16; it++) {
        int idx = it * 256 + tid;
        int m = idx >> 6, pair = idx & 63;
        const float* pm = smem + m * EPL2 + pair;
        float m0 = pm[0 * CPLN2];
        float m1 = pm[1 * CPLN2];
        float m2 = pm[2 * CPLN2];
        float m3 = pm[3 * CPLN2];
        int o = o0 + m;
        float dem = dm[o], bv = bias[o];
        float2 v;
        v.x = lrelu2((m0 + m1 + m2) * dem + bv);
        v.y = lrelu2((m1 - m2 - m3) * dem + bv);
        int row = h0 + (pair >> 5);
        int col = (pair & 31) * 2;
        *reinterpret_cast<float2*>(out + ((size_t)b * 512 + o) * 4096 + row * 64 + col) = v;
    }
}

// ---------------- launch ----------------
extern "C" void kernel_launch(void* const* d_in, const int* in_sizes, int n_in,
                              void* d_out, int out_size) {
    const float* x      = (const float*)d_in[0];
    const float* latent = (const float*)d_in[1];
    const float* noise  = (const float*)d_in[2];
    const float* aw     = (const float*)d_in[3];
    const float* ab     = (const float*)d_in[4];
    const float* cw     = (const float*)d_in[5];
    const float* nw     = (const float*)d_in[6];
    const float* bias   = (const float*)d_in[7];
    float* out = (float*)d_out;

    cudaFuncSetAttribute(conv_kernel, cudaFuncAttributeMaxDynamicSharedMemorySize,
                         SMEMF2 * (int)sizeof(float));

    style_kernel<<<16, 512>>>(latent, aw, ab);
    prep1_kernel<<<576, 512>>>(cw);
    prep2_kernel<<<dim3(65, 16), 256>>>(x, noise, nw);
    conv_kernel<<<dim3(32, 8, 16), 256, SMEMF2 * sizeof(float)>>>(bias, out);
}